// round 6
// baseline (speedup 1.0000x reference)
#include <cuda_runtime.h>
#include <cstdint>

// ---------------------------------------------------------------------------
// CompressedGNN: 2-layer GCN + linear classifier.
//   h1 = gcn(x, W1, b1); relu
//   h2 = gcn(h1, W2, b2)
//   out = h2 @ Wc + bc
// gcn(x,W,b): h = x@W; deg = 1 + indeg(dst); dinv = rsqrt(deg);
//   agg[i] = sum_{e: dst=i} h[src]*dinv[src]*dinv[i] + h[i]*dinv[i]^2 + b
//
// edge_index arrives as INT32 (JAX x64 disabled downcasts the requested int64).
// Scratch lives in __device__ globals referenced directly by kernels.
// ---------------------------------------------------------------------------

#define MAX_N 10000
#define MAX_E 160000
#define D_HID 512

__device__ float g_h[MAX_N * D_HID];     // post-GEMM features
__device__ float g_a[MAX_N * D_HID];     // post-aggregation features
__device__ float g_dinv[MAX_N];
__device__ int   g_cnt[MAX_N];
__device__ int   g_rowptr[MAX_N + 1];
__device__ int   g_cursor[MAX_N];
__device__ int   g_col[MAX_E];

// ---------------------------------------------------------------------------
__global__ void zero_cnt_kernel(int n) {
    int i = blockIdx.x * blockDim.x + threadIdx.x;
    if (i < n) g_cnt[i] = 0;
}

__global__ void count_kernel(const int* __restrict__ ei, int E, int n) {
    int e = blockIdx.x * blockDim.x + threadIdx.x;
    if (e < E) {
        int d = ei[E + e];
        if (d >= 0 && d < n) atomicAdd(&g_cnt[d], 1);
    }
}

// Single-block scan: rowptr (exclusive), cursor copy, dinv.
__global__ void scan_kernel(int n) {
    __shared__ int part[1024];
    int tid = threadIdx.x;
    int CH = (n + 1023) / 1024;
    int base = tid * CH;
    int s = 0;
    for (int i = 0; i < CH; ++i) {
        int idx = base + i;
        if (idx < n) s += g_cnt[idx];
    }
    part[tid] = s;
    __syncthreads();
    // Hillis-Steele inclusive scan over 1024 partials
    for (int off = 1; off < 1024; off <<= 1) {
        int add = (tid >= off) ? part[tid - off] : 0;
        __syncthreads();
        part[tid] += add;
        __syncthreads();
    }
    int run = part[tid] - s;  // exclusive prefix for this chunk
    for (int i = 0; i < CH; ++i) {
        int idx = base + i;
        if (idx < n) {
            g_rowptr[idx] = run;
            g_cursor[idx] = run;
            int c = g_cnt[idx];
            g_dinv[idx] = rsqrtf(1.0f + (float)c);
            run += c;
        }
    }
    if (tid == 0) g_rowptr[n] = part[1023];
}

__global__ void fill_kernel(const int* __restrict__ ei, int E, int n) {
    int e = blockIdx.x * blockDim.x + threadIdx.x;
    if (e < E) {
        int s = ei[e];
        int d = ei[E + e];
        if (d >= 0 && d < n && s >= 0 && s < n) {
            int pos = atomicAdd(&g_cursor[d], 1);
            g_col[pos] = s;
        }
    }
}

// ---------------------------------------------------------------------------
// SGEMM body: C[M,N] = A[M,K] @ B[K,N] (+ bias). 128x128 tile, 8x8 per thread.
#define BM 128
#define BN 128
#define BK 8
#define TM 8
#define TN 8

__device__ __forceinline__ void sgemm_body(
    const float* __restrict__ A, const float* __restrict__ B,
    const float* __restrict__ bias, float* __restrict__ C,
    int M, int N, int K)
{
    __shared__ float As[BK][BM];
    __shared__ float Bs[BK][BN];

    int tid = threadIdx.x;
    int bm = blockIdx.y * BM;
    int bn = blockIdx.x * BN;
    int tx = tid & 15;
    int ty = tid >> 4;

    int arow = tid >> 1;         // 128 rows, 2 threads per row
    int acol = (tid & 1) * 4;    // each loads float4
    int brow = tid >> 5;         // 8 rows
    int bcol = (tid & 31) * 4;   // 128 cols

    float acc[TM][TN];
#pragma unroll
    for (int i = 0; i < TM; ++i)
#pragma unroll
        for (int j = 0; j < TN; ++j) acc[i][j] = 0.0f;

    for (int k0 = 0; k0 < K; k0 += BK) {
        float4 av = make_float4(0.f, 0.f, 0.f, 0.f);
        int gr = bm + arow;
        if (gr < M) av = *(const float4*)&A[(size_t)gr * K + k0 + acol];
        As[acol + 0][arow] = av.x;
        As[acol + 1][arow] = av.y;
        As[acol + 2][arow] = av.z;
        As[acol + 3][arow] = av.w;
        int gc = bn + bcol;
        int krow = k0 + brow;
        float4 bv = make_float4(0.f, 0.f, 0.f, 0.f);
        if (gc + 3 < N) {
            bv = *(const float4*)&B[(size_t)krow * N + gc];
        } else if (gc < N) {
            const float* bp = &B[(size_t)krow * N];
            bv.x = bp[gc];
            if (gc + 1 < N) bv.y = bp[gc + 1];
            if (gc + 2 < N) bv.z = bp[gc + 2];
        }
        *(float4*)&Bs[brow][bcol] = bv;
        __syncthreads();

#pragma unroll
        for (int k = 0; k < BK; ++k) {
            float a0[TM], b0[TN];
#pragma unroll
            for (int i = 0; i < TM; ++i) a0[i] = As[k][ty * TM + i];
#pragma unroll
            for (int j = 0; j < TN; ++j) b0[j] = Bs[k][tx * TN + j];
#pragma unroll
            for (int i = 0; i < TM; ++i)
#pragma unroll
                for (int j = 0; j < TN; ++j)
                    acc[i][j] += a0[i] * b0[j];
        }
        __syncthreads();
    }

#pragma unroll
    for (int i = 0; i < TM; ++i) {
        int r = bm + ty * TM + i;
        if (r >= M) continue;
#pragma unroll
        for (int j = 0; j < TN; ++j) {
            int c = bn + tx * TN + j;
            if (c < N) {
                float v = acc[i][j];
                if (bias) v += bias[c];
                C[(size_t)r * N + c] = v;
            }
        }
    }
}

// GEMM variants addressing device-global scratch directly:
__global__ __launch_bounds__(256, 2) void sgemm_x_to_h(
    const float* __restrict__ A, const float* __restrict__ B, int M, int N, int K)
{
    sgemm_body(A, B, nullptr, g_h, M, N, K);
}

__global__ __launch_bounds__(256, 2) void sgemm_a_to_h(
    const float* __restrict__ B, int M, int N, int K)
{
    sgemm_body(g_a, B, nullptr, g_h, M, N, K);
}

__global__ __launch_bounds__(256, 2) void sgemm_a_to_out(
    const float* __restrict__ B, const float* __restrict__ bias,
    float* __restrict__ C, int M, int N, int K)
{
    sgemm_body(g_a, B, bias, C, M, N, K);
}

// ---------------------------------------------------------------------------
// Aggregation: one block per node, 128 threads, each owns 4 feats via float4.
__global__ __launch_bounds__(128) void agg_kernel(
    const float* __restrict__ bias, int relu)
{
    int i = blockIdx.x;
    int tid = threadIdx.x;
    const float4* h4 = (const float4*)g_h;
    float di = g_dinv[i];
    int beg = g_rowptr[i];
    int end = g_rowptr[i + 1];

    float4 acc = make_float4(0.f, 0.f, 0.f, 0.f);
    for (int j = beg; j < end; ++j) {
        int s = g_col[j];
        float w = g_dinv[s] * di;
        float4 v = h4[(size_t)s * (D_HID / 4) + tid];
        acc.x += v.x * w;
        acc.y += v.y * w;
        acc.z += v.z * w;
        acc.w += v.w * w;
    }
    float sw = di * di;
    float4 self = h4[(size_t)i * (D_HID / 4) + tid];
    acc.x += self.x * sw;
    acc.y += self.y * sw;
    acc.z += self.z * sw;
    acc.w += self.w * sw;
    const float4* b4 = (const float4*)bias;
    float4 bb = b4[tid];
    acc.x += bb.x; acc.y += bb.y; acc.z += bb.z; acc.w += bb.w;
    if (relu) {
        acc.x = fmaxf(acc.x, 0.f);
        acc.y = fmaxf(acc.y, 0.f);
        acc.z = fmaxf(acc.z, 0.f);
        acc.w = fmaxf(acc.w, 0.f);
    }
    ((float4*)g_a)[(size_t)i * (D_HID / 4) + tid] = acc;
}

// ---------------------------------------------------------------------------
extern "C" void kernel_launch(void* const* d_in, const int* in_sizes, int n_in,
                              void* d_out, int out_size) {
    const float* x  = (const float*)d_in[0];
    const int*   ei = (const int*)d_in[1];     // int32! (JAX x64 disabled)
    const float* W1 = (const float*)d_in[2];
    const float* b1 = (const float*)d_in[3];
    const float* W2 = (const float*)d_in[4];
    const float* b2 = (const float*)d_in[5];
    const float* Wc = (const float*)d_in[6];
    const float* bc = (const float*)d_in[7];
    float* out = (float*)d_out;

    int N = in_sizes[0] / D_HID;          // 10000
    int E = in_sizes[1] / 2;              // 160000
    int d_out_dim = in_sizes[6] / D_HID;  // 100

    // 1. CSR build
    zero_cnt_kernel<<<(N + 255) / 256, 256>>>(N);
    count_kernel<<<(E + 255) / 256, 256>>>(ei, E, N);
    scan_kernel<<<1, 1024>>>(N);
    fill_kernel<<<(E + 255) / 256, 256>>>(ei, E, N);

    dim3 gemm_block(256);
    dim3 gemm_grid_hid((D_HID + BN - 1) / BN, (N + BM - 1) / BM);
    dim3 gemm_grid_out((d_out_dim + BN - 1) / BN, (N + BM - 1) / BM);

    // 2. Layer 1:  g_h = x @ W1 ; g_a = agg(g_h) + b1, relu
    sgemm_x_to_h<<<gemm_grid_hid, gemm_block>>>(x, W1, N, D_HID, D_HID);
    agg_kernel<<<N, 128>>>(b1, 1);

    // 3. Layer 2:  g_h = g_a @ W2 ; g_a = agg(g_h) + b2
    sgemm_a_to_h<<<gemm_grid_hid, gemm_block>>>(W2, N, D_HID, D_HID);
    agg_kernel<<<N, 128>>>(b2, 0);

    // 4. Classifier: out = g_a @ Wc + bc
    sgemm_a_to_out<<<gemm_grid_out, gemm_block>>>(Wc, bc, out, N, d_out_dim, D_HID);
}

// round 8
// speedup vs baseline: 1.8507x; 1.8507x over previous
#include <cuda_runtime.h>
#include <cuda_bf16.h>
#include <cstdint>

// ---------------------------------------------------------------------------
// CompressedGNN on GB300 (sm_103 plain target — no tcgen05 in harness PTX).
// GEMMs: mma.sync bf16 (HMMA), split-precision x3 -> fp32 accum.
// Aggregation: CSR gather (atomic-free), fused bf16 hi/lo split output.
// ---------------------------------------------------------------------------

#define NNODES 10000
#define MAXE   160000
#define DH     512
#define NPADC  128

__device__ float g_h[NNODES * DH];              // fp32 GEMM output
__device__ uint4 g_ahi[NNODES * DH / 8];        // split A operand (8 bf16/uint4)
__device__ uint4 g_alo[NNODES * DH / 8];
__device__ uint4 g_w1hi[DH * DH / 8];           // transposed split weights [N][K]
__device__ uint4 g_w1lo[DH * DH / 8];
__device__ uint4 g_w2hi[DH * DH / 8];
__device__ uint4 g_w2lo[DH * DH / 8];
__device__ uint4 g_wchi[NPADC * DH / 8];
__device__ uint4 g_wclo[NPADC * DH / 8];
__device__ float g_dinv[NNODES];
__device__ int   g_cnt[NNODES];
__device__ int   g_rowptr[NNODES + 1];
__device__ int   g_cursor[NNODES];
__device__ int   g_col[MAXE];

// ---------------------------------------------------------------------------
__device__ __forceinline__ uint32_t smem_to_u32(const void* p) {
    uint32_t a;
    asm("{ .reg .u64 t; cvta.to.shared.u64 t, %1; cvt.u32.u64 %0, t; }"
        : "=r"(a) : "l"(p));
    return a;
}

__device__ __forceinline__ void ldmat_x4(uint32_t (&r)[4], uint32_t addr) {
    asm volatile("ldmatrix.sync.aligned.m8n8.x4.shared.b16 {%0,%1,%2,%3}, [%4];"
                 : "=r"(r[0]), "=r"(r[1]), "=r"(r[2]), "=r"(r[3]) : "r"(addr));
}

__device__ __forceinline__ void mma_bf16(float (&d)[4], const uint32_t (&a)[4],
                                         uint32_t b0, uint32_t b1) {
    asm volatile("mma.sync.aligned.m16n8k16.row.col.f32.bf16.bf16.f32 "
                 "{%0,%1,%2,%3}, {%4,%5,%6,%7}, {%8,%9}, {%0,%1,%2,%3};"
                 : "+f"(d[0]), "+f"(d[1]), "+f"(d[2]), "+f"(d[3])
                 : "r"(a[0]), "r"(a[1]), "r"(a[2]), "r"(a[3]), "r"(b0), "r"(b1));
}

__device__ __forceinline__ void cp16(uint32_t dst, const void* src, bool valid) {
    int sz = valid ? 16 : 0;
    asm volatile("cp.async.cg.shared.global [%0], [%1], 16, %2;"
                 :: "r"(dst), "l"(src), "r"(sz) : "memory");
}
#define CP_COMMIT() asm volatile("cp.async.commit_group;" ::: "memory")
#define CP_WAIT0()  asm volatile("cp.async.wait_group 0;" ::: "memory")
#define CP_WAIT1()  asm volatile("cp.async.wait_group 1;" ::: "memory")

// ---------------------------------------------------------------------------
// CSR build
// ---------------------------------------------------------------------------
__global__ void zero_cnt_kernel(int n) {
    int i = blockIdx.x * blockDim.x + threadIdx.x;
    if (i < n) g_cnt[i] = 0;
}

__global__ void count_kernel(const int* __restrict__ ei, int E, int n) {
    int e = blockIdx.x * blockDim.x + threadIdx.x;
    if (e < E) {
        int d = ei[E + e];
        if (d >= 0 && d < n) atomicAdd(&g_cnt[d], 1);
    }
}

__global__ void scan_kernel(int n) {
    __shared__ int part[1024];
    int tid = threadIdx.x;
    int CH = (n + 1023) / 1024;
    int base = tid * CH;
    int s = 0;
    for (int i = 0; i < CH; ++i) {
        int idx = base + i;
        if (idx < n) s += g_cnt[idx];
    }
    part[tid] = s;
    __syncthreads();
    for (int off = 1; off < 1024; off <<= 1) {
        int add = (tid >= off) ? part[tid - off] : 0;
        __syncthreads();
        part[tid] += add;
        __syncthreads();
    }
    int run = part[tid] - s;
    for (int i = 0; i < CH; ++i) {
        int idx = base + i;
        if (idx < n) {
            g_rowptr[idx] = run;
            g_cursor[idx] = run;
            int c = g_cnt[idx];
            g_dinv[idx] = rsqrtf(1.0f + (float)c);
            run += c;
        }
    }
    if (tid == 0) g_rowptr[n] = part[1023];
}

__global__ void fill_kernel(const int* __restrict__ ei, int E, int n) {
    int e = blockIdx.x * blockDim.x + threadIdx.x;
    if (e < E) {
        int s = ei[e];
        int d = ei[E + e];
        if (d >= 0 && d < n && s >= 0 && s < n) {
            int pos = atomicAdd(&g_cursor[d], 1);
            g_col[pos] = s;
        }
    }
}

// ---------------------------------------------------------------------------
// bf16 split prep
// ---------------------------------------------------------------------------
__device__ __forceinline__ void split_bf16(float v, __nv_bfloat16& hi, __nv_bfloat16& lo) {
    hi = __float2bfloat16(v);
    lo = __float2bfloat16(v - __bfloat162float(hi));
}

__global__ void conv_x_kernel(const float* __restrict__ x) {
    int idx = blockIdx.x * blockDim.x + threadIdx.x;
    int total = NNODES * DH / 8;
    if (idx >= total) return;
    const float4* p = (const float4*)x;
    float4 a = p[idx * 2], b = p[idx * 2 + 1];
    float v[8] = {a.x, a.y, a.z, a.w, b.x, b.y, b.z, b.w};
    __nv_bfloat16 hi[8], lo[8];
#pragma unroll
    for (int j = 0; j < 8; ++j) split_bf16(v[j], hi[j], lo[j]);
    g_ahi[idx] = *(uint4*)hi;
    g_alo[idx] = *(uint4*)lo;
}

// Transpose + split: W [DH x N] -> [Npad x DH] bf16 hi/lo. which: 0/1/2.
__global__ void prep_w_kernel(const float* __restrict__ W, int N, int which) {
    __shared__ float t[32][33];
    int k0 = blockIdx.x * 32, n0 = blockIdx.y * 32;
    int tx = threadIdx.x, ty = threadIdx.y;
    int k = k0 + ty, n = n0 + tx;
    float v = 0.0f;
    if (n < N) v = W[(size_t)k * N + n];
    t[ty][tx] = v;
    __syncthreads();
    int on = n0 + ty, ok = k0 + tx;
    float w = t[tx][ty];
    __nv_bfloat16 hi, lo;
    split_bf16(w, hi, lo);
    __nv_bfloat16 *dh, *dl;
    if (which == 0)      { dh = (__nv_bfloat16*)g_w1hi; dl = (__nv_bfloat16*)g_w1lo; }
    else if (which == 1) { dh = (__nv_bfloat16*)g_w2hi; dl = (__nv_bfloat16*)g_w2lo; }
    else                 { dh = (__nv_bfloat16*)g_wchi; dl = (__nv_bfloat16*)g_wclo; }
    dh[(size_t)on * DH + ok] = hi;
    dl[(size_t)on * DH + ok] = lo;
}

// ---------------------------------------------------------------------------
// HMMA GEMM: C[10000, Ncols] = A(split) @ W^T(split). 128x128 CTA tile,
// BK=32, 8 warps (2x4), warp tile 64x32, double-buffered cp.async.
// 3 passes accumulate AhiBhi + AhiBlo + AloBhi into fp32 regs.
// ---------------------------------------------------------------------------
#define BMt 128
#define BNt 128
#define BKt 32
#define ROWB 80                 // padded smem row bytes (64B data + 16B pad)
#define NCHUNK (DH / BKt)       // 16
#define TOTIT (3 * NCHUNK)      // 48

__global__ __launch_bounds__(256, 2)
void mma_gemm_kernel(int which, const float* __restrict__ bias,
                     float* __restrict__ extout, int Nvalid)
{
    __shared__ __align__(128) char sA[2][BMt * ROWB];
    __shared__ __align__(128) char sB[2][BNt * ROWB];

    int tid = threadIdx.x, lane = tid & 31, wid = tid >> 5;
    int m0 = blockIdx.y * BMt, n0 = blockIdx.x * BNt;
    int warp_m = (wid >> 2) * 64, warp_n = (wid & 3) * 32;

    const uint4 *Wh, *Wl;
    if (which == 0)      { Wh = g_w1hi; Wl = g_w1lo; }
    else if (which == 1) { Wh = g_w2hi; Wl = g_w2lo; }
    else                 { Wh = g_wchi; Wl = g_wclo; }

    uint32_t aBase = smem_to_u32(sA);
    uint32_t bBase = smem_to_u32(sB);

    // loader mapping: thread -> row r, two 16B chunks (j0, j0+1)
    int r  = tid >> 1;
    int j0 = (tid & 1) * 2;
    uint32_t dOff0 = (uint32_t)(r * ROWB + j0 * 16);
    bool avalid = (m0 + r) < NNODES;
    size_t aRowIdx = (size_t)(m0 + r) * (DH / 8) + j0;
    size_t bRowIdx = (size_t)(n0 + r) * (DH / 8) + j0;

    float acc[4][4][4];
#pragma unroll
    for (int a = 0; a < 4; ++a)
#pragma unroll
        for (int b = 0; b < 4; ++b)
#pragma unroll
            for (int c = 0; c < 4; ++c) acc[a][b][c] = 0.0f;

#define ISSUE(it, buf) do {                                                   \
        int _p = (it) >> 4, _c = (it) & 15;                                   \
        const uint4* _As = ((_p == 2) ? g_alo : g_ahi) + aRowIdx + _c * 4;    \
        const uint4* _Bs = ((_p == 1) ? Wl : Wh) + bRowIdx + _c * 4;          \
        uint32_t _da = aBase + (buf) * (BMt * ROWB) + dOff0;                  \
        uint32_t _db = bBase + (buf) * (BNt * ROWB) + dOff0;                  \
        cp16(_da,      _As,     avalid);                                      \
        cp16(_da + 16, _As + 1, avalid);                                      \
        cp16(_db,      _Bs,     true);                                        \
        cp16(_db + 16, _Bs + 1, true);                                        \
    } while (0)

    ISSUE(0, 0);
    CP_COMMIT();

    for (int it = 0; it < TOTIT; ++it) {
        int buf = it & 1;
        if (it + 1 < TOTIT) {
            ISSUE(it + 1, buf ^ 1);
            CP_COMMIT();
            CP_WAIT1();
        } else {
            CP_WAIT0();
        }
        __syncthreads();

        uint32_t aT = aBase + buf * (BMt * ROWB);
        uint32_t bT = bBase + buf * (BNt * ROWB);
#pragma unroll
        for (int ks = 0; ks < 2; ++ks) {
            uint32_t af[4][4], bf[2][4];
#pragma unroll
            for (int mf = 0; mf < 4; ++mf) {
                int row = warp_m + mf * 16 + (lane & 15);
                ldmat_x4(af[mf], aT + row * ROWB + ks * 32 + ((lane >> 4) * 16));
            }
#pragma unroll
            for (int nb = 0; nb < 2; ++nb) {
                int nrow = warp_n + nb * 16 + ((lane >> 4) << 3) + (lane & 7);
                ldmat_x4(bf[nb], bT + nrow * ROWB + ks * 32 + (((lane >> 3) & 1) * 16));
            }
#pragma unroll
            for (int mf = 0; mf < 4; ++mf)
#pragma unroll
                for (int nf = 0; nf < 4; ++nf)
                    mma_bf16(acc[mf][nf], af[mf],
                             bf[nf >> 1][(nf & 1) * 2], bf[nf >> 1][(nf & 1) * 2 + 1]);
        }
        __syncthreads();
    }
#undef ISSUE

    // epilogue
#pragma unroll
    for (int mf = 0; mf < 4; ++mf) {
        int rr = m0 + warp_m + mf * 16 + (lane >> 2);
#pragma unroll
        for (int nf = 0; nf < 4; ++nf) {
            int cc = n0 + warp_n + nf * 8 + (lane & 3) * 2;
            float d0 = acc[mf][nf][0], d1 = acc[mf][nf][1];
            float d2 = acc[mf][nf][2], d3 = acc[mf][nf][3];
            if (extout) {
                if (rr < NNODES) {
                    if (cc < Nvalid)     extout[(size_t)rr * Nvalid + cc]     = d0 + bias[cc];
                    if (cc + 1 < Nvalid) extout[(size_t)rr * Nvalid + cc + 1] = d1 + bias[cc + 1];
                }
                if (rr + 8 < NNODES) {
                    if (cc < Nvalid)     extout[(size_t)(rr + 8) * Nvalid + cc]     = d2 + bias[cc];
                    if (cc + 1 < Nvalid) extout[(size_t)(rr + 8) * Nvalid + cc + 1] = d3 + bias[cc + 1];
                }
            } else {
                if (rr < NNODES)     *(float2*)&g_h[(size_t)rr * DH + cc]       = make_float2(d0, d1);
                if (rr + 8 < NNODES) *(float2*)&g_h[(size_t)(rr + 8) * DH + cc] = make_float2(d2, d3);
            }
        }
    }
}

// ---------------------------------------------------------------------------
// Aggregation: one block per node; writes split bf16 for next GEMM.
// ---------------------------------------------------------------------------
__global__ __launch_bounds__(128) void agg_kernel(
    const float* __restrict__ bias, int relu)
{
    int i = blockIdx.x;
    int tid = threadIdx.x;
    const float4* h4 = (const float4*)g_h;
    float di = g_dinv[i];
    int beg = g_rowptr[i];
    int end = g_rowptr[i + 1];

    float4 acc = make_float4(0.f, 0.f, 0.f, 0.f);
    for (int j = beg; j < end; ++j) {
        int s = g_col[j];
        float w = g_dinv[s] * di;
        float4 v = h4[(size_t)s * (DH / 4) + tid];
        acc.x += v.x * w;
        acc.y += v.y * w;
        acc.z += v.z * w;
        acc.w += v.w * w;
    }
    float sw = di * di;
    float4 self = h4[(size_t)i * (DH / 4) + tid];
    acc.x += self.x * sw;
    acc.y += self.y * sw;
    acc.z += self.z * sw;
    acc.w += self.w * sw;
    const float4* b4 = (const float4*)bias;
    float4 bb = b4[tid];
    acc.x += bb.x; acc.y += bb.y; acc.z += bb.z; acc.w += bb.w;
    if (relu) {
        acc.x = fmaxf(acc.x, 0.f);
        acc.y = fmaxf(acc.y, 0.f);
        acc.z = fmaxf(acc.z, 0.f);
        acc.w = fmaxf(acc.w, 0.f);
    }
    float v[4] = {acc.x, acc.y, acc.z, acc.w};
    __nv_bfloat16 hi[4], lo[4];
#pragma unroll
    for (int j = 0; j < 4; ++j) split_bf16(v[j], hi[j], lo[j]);
    ((uint2*)g_ahi)[(size_t)i * (DH / 4) + tid] = *(uint2*)hi;
    ((uint2*)g_alo)[(size_t)i * (DH / 4) + tid] = *(uint2*)lo;
}

// ---------------------------------------------------------------------------
extern "C" void kernel_launch(void* const* d_in, const int* in_sizes, int n_in,
                              void* d_out, int out_size) {
    const float* x  = (const float*)d_in[0];
    const int*   ei = (const int*)d_in[1];     // int32 (JAX x64 disabled)
    const float* W1 = (const float*)d_in[2];
    const float* b1 = (const float*)d_in[3];
    const float* W2 = (const float*)d_in[4];
    const float* b2 = (const float*)d_in[5];
    const float* Wc = (const float*)d_in[6];
    const float* bc = (const float*)d_in[7];
    float* out = (float*)d_out;

    int N = in_sizes[0] / DH;             // 10000
    int E = in_sizes[1] / 2;              // 160000
    int d_out_dim = in_sizes[6] / DH;     // 100

    // CSR build
    zero_cnt_kernel<<<(N + 255) / 256, 256>>>(N);
    count_kernel<<<(E + 255) / 256, 256>>>(ei, E, N);
    scan_kernel<<<1, 1024>>>(N);
    fill_kernel<<<(E + 255) / 256, 256>>>(ei, E, N);

    // operand prep
    conv_x_kernel<<<(N * DH / 8 + 255) / 256, 256>>>(x);
    dim3 tb(32, 32);
    prep_w_kernel<<<dim3(DH / 32, DH / 32), tb>>>(W1, DH, 0);
    prep_w_kernel<<<dim3(DH / 32, DH / 32), tb>>>(W2, DH, 1);
    prep_w_kernel<<<dim3(DH / 32, NPADC / 32), tb>>>(Wc, d_out_dim, 2);

    int mblocks = (N + BMt - 1) / BMt;    // 79

    // Layer 1
    mma_gemm_kernel<<<dim3(DH / BNt, mblocks), 256>>>(0, nullptr, nullptr, DH);
    agg_kernel<<<N, 128>>>(b1, 1);

    // Layer 2
    mma_gemm_kernel<<<dim3(DH / BNt, mblocks), 256>>>(1, nullptr, nullptr, DH);
    agg_kernel<<<N, 128>>>(b2, 0);

    // Classifier
    mma_gemm_kernel<<<dim3(1, mblocks), 256>>>(2, bc, out, d_out_dim);
}

// round 9
// speedup vs baseline: 2.4239x; 1.3097x over previous
#include <cuda_runtime.h>
#include <cuda_bf16.h>
#include <cstdint>

// ---------------------------------------------------------------------------
// CompressedGNN on GB300 (sm_103 plain target — no tcgen05 in harness PTX).
// GEMMs: mma.sync bf16 (HMMA), split-precision x3 FUSED into one k-loop.
// Aggregation: CSR gather (atomic-free), fused bf16 hi/lo split output.
// ---------------------------------------------------------------------------

#define NNODES 10000
#define MAXE   160000
#define DH     512
#define NPADC  128

__device__ float g_h[NNODES * DH];              // fp32 GEMM output
__device__ uint4 g_ahi[NNODES * DH / 8];        // split A operand (8 bf16/uint4)
__device__ uint4 g_alo[NNODES * DH / 8];
__device__ uint4 g_w1hi[DH * DH / 8];           // transposed split weights [N][K]
__device__ uint4 g_w1lo[DH * DH / 8];
__device__ uint4 g_w2hi[DH * DH / 8];
__device__ uint4 g_w2lo[DH * DH / 8];
__device__ uint4 g_wchi[NPADC * DH / 8];
__device__ uint4 g_wclo[NPADC * DH / 8];
__device__ float g_dinv[NNODES];
__device__ int   g_cnt[NNODES];
__device__ int   g_rowptr[NNODES + 1];
__device__ int   g_cursor[NNODES];
__device__ int   g_col[MAXE];

// ---------------------------------------------------------------------------
__device__ __forceinline__ uint32_t smem_to_u32(const void* p) {
    uint32_t a;
    asm("{ .reg .u64 t; cvta.to.shared.u64 t, %1; cvt.u32.u64 %0, t; }"
        : "=r"(a) : "l"(p));
    return a;
}

__device__ __forceinline__ void ldmat_x4(uint32_t (&r)[4], uint32_t addr) {
    asm volatile("ldmatrix.sync.aligned.m8n8.x4.shared.b16 {%0,%1,%2,%3}, [%4];"
                 : "=r"(r[0]), "=r"(r[1]), "=r"(r[2]), "=r"(r[3]) : "r"(addr));
}

__device__ __forceinline__ void mma_bf16(float (&d)[4], const uint32_t (&a)[4],
                                         uint32_t b0, uint32_t b1) {
    asm volatile("mma.sync.aligned.m16n8k16.row.col.f32.bf16.bf16.f32 "
                 "{%0,%1,%2,%3}, {%4,%5,%6,%7}, {%8,%9}, {%0,%1,%2,%3};"
                 : "+f"(d[0]), "+f"(d[1]), "+f"(d[2]), "+f"(d[3])
                 : "r"(a[0]), "r"(a[1]), "r"(a[2]), "r"(a[3]), "r"(b0), "r"(b1));
}

__device__ __forceinline__ void cp16(uint32_t dst, const void* src, bool valid) {
    int sz = valid ? 16 : 0;
    asm volatile("cp.async.cg.shared.global [%0], [%1], 16, %2;"
                 :: "r"(dst), "l"(src), "r"(sz) : "memory");
}
#define CP_COMMIT() asm volatile("cp.async.commit_group;" ::: "memory")
#define CP_WAIT0()  asm volatile("cp.async.wait_group 0;" ::: "memory")
#define CP_WAIT1()  asm volatile("cp.async.wait_group 1;" ::: "memory")

// ---------------------------------------------------------------------------
// CSR build
// ---------------------------------------------------------------------------
__global__ void zero_cnt_kernel(int n) {
    int i = blockIdx.x * blockDim.x + threadIdx.x;
    if (i < n) g_cnt[i] = 0;
}

__global__ void count_kernel(const int* __restrict__ ei, int E, int n) {
    int e = blockIdx.x * blockDim.x + threadIdx.x;
    if (e < E) {
        int d = ei[E + e];
        if (d >= 0 && d < n) atomicAdd(&g_cnt[d], 1);
    }
}

__global__ void scan_kernel(int n) {
    __shared__ int part[1024];
    int tid = threadIdx.x;
    int CH = (n + 1023) / 1024;
    int base = tid * CH;
    int s = 0;
    for (int i = 0; i < CH; ++i) {
        int idx = base + i;
        if (idx < n) s += g_cnt[idx];
    }
    part[tid] = s;
    __syncthreads();
    for (int off = 1; off < 1024; off <<= 1) {
        int add = (tid >= off) ? part[tid - off] : 0;
        __syncthreads();
        part[tid] += add;
        __syncthreads();
    }
    int run = part[tid] - s;
    for (int i = 0; i < CH; ++i) {
        int idx = base + i;
        if (idx < n) {
            g_rowptr[idx] = run;
            g_cursor[idx] = run;
            int c = g_cnt[idx];
            g_dinv[idx] = rsqrtf(1.0f + (float)c);
            run += c;
        }
    }
    if (tid == 0) g_rowptr[n] = part[1023];
}

__global__ void fill_kernel(const int* __restrict__ ei, int E, int n) {
    int e = blockIdx.x * blockDim.x + threadIdx.x;
    if (e < E) {
        int s = ei[e];
        int d = ei[E + e];
        if (d >= 0 && d < n && s >= 0 && s < n) {
            int pos = atomicAdd(&g_cursor[d], 1);
            g_col[pos] = s;
        }
    }
}

// ---------------------------------------------------------------------------
// bf16 split prep
// ---------------------------------------------------------------------------
__device__ __forceinline__ void split_bf16(float v, __nv_bfloat16& hi, __nv_bfloat16& lo) {
    hi = __float2bfloat16(v);
    lo = __float2bfloat16(v - __bfloat162float(hi));
}

__global__ void conv_x_kernel(const float* __restrict__ x) {
    int idx = blockIdx.x * blockDim.x + threadIdx.x;
    int total = NNODES * DH / 8;
    if (idx >= total) return;
    const float4* p = (const float4*)x;
    float4 a = p[idx * 2], b = p[idx * 2 + 1];
    float v[8] = {a.x, a.y, a.z, a.w, b.x, b.y, b.z, b.w};
    __nv_bfloat16 hi[8], lo[8];
#pragma unroll
    for (int j = 0; j < 8; ++j) split_bf16(v[j], hi[j], lo[j]);
    g_ahi[idx] = *(uint4*)hi;
    g_alo[idx] = *(uint4*)lo;
}

// Transpose + split: W [DH x N] -> [Npad x DH] bf16 hi/lo. which: 0/1/2.
__global__ void prep_w_kernel(const float* __restrict__ W, int N, int which) {
    __shared__ float t[32][33];
    int k0 = blockIdx.x * 32, n0 = blockIdx.y * 32;
    int tx = threadIdx.x, ty = threadIdx.y;
    int k = k0 + ty, n = n0 + tx;
    float v = 0.0f;
    if (n < N) v = W[(size_t)k * N + n];
    t[ty][tx] = v;
    __syncthreads();
    int on = n0 + ty, ok = k0 + tx;
    float w = t[tx][ty];
    __nv_bfloat16 hi, lo;
    split_bf16(w, hi, lo);
    __nv_bfloat16 *dh, *dl;
    if (which == 0)      { dh = (__nv_bfloat16*)g_w1hi; dl = (__nv_bfloat16*)g_w1lo; }
    else if (which == 1) { dh = (__nv_bfloat16*)g_w2hi; dl = (__nv_bfloat16*)g_w2lo; }
    else                 { dh = (__nv_bfloat16*)g_wchi; dl = (__nv_bfloat16*)g_wclo; }
    dh[(size_t)on * DH + ok] = hi;
    dl[(size_t)on * DH + ok] = lo;
}

// ---------------------------------------------------------------------------
// HMMA GEMM, fused split passes. 128x128 CTA tile, BK=16, 8 warps (2x4),
// warp tile 64x32. Per k-chunk: load Ahi/Alo/Bhi/Blo, do HH+HL+LH (48 mma).
// ---------------------------------------------------------------------------
#define BMt 128
#define BNt 128
#define BKt 16
#define ROWB 48                       // 32B data + 16B pad per row
#define TILEB (128 * ROWB)            // 6144 B per operand tile
#define STAGEB (4 * TILEB)            // Ahi|Alo|Bhi|Blo
#define NCH (DH / BKt)                // 32 k-chunks

__global__ __launch_bounds__(256, 2)
void mma_gemm_kernel(int which, const float* __restrict__ bias,
                     float* __restrict__ extout, int Nvalid)
{
    __shared__ __align__(128) char sMem[2 * STAGEB];   // 49152 B exactly

    int tid = threadIdx.x, lane = tid & 31, wid = tid >> 5;
    int m0 = blockIdx.y * BMt, n0 = blockIdx.x * BNt;
    int warp_m = (wid >> 2) * 64, warp_n = (wid & 3) * 32;

    const uint4 *Wh, *Wl;
    if (which == 0)      { Wh = g_w1hi; Wl = g_w1lo; }
    else if (which == 1) { Wh = g_w2hi; Wl = g_w2lo; }
    else                 { Wh = g_wchi; Wl = g_wclo; }

    uint32_t base = smem_to_u32(sMem);

    // loader: thread -> row r, 16B chunk j of each of the 4 tiles
    int r = tid >> 1;
    int j = tid & 1;
    uint32_t dOff = (uint32_t)(r * ROWB + j * 16);
    bool avalid = (m0 + r) < NNODES;
    size_t aRow = (size_t)(m0 + r) * (DH / 8) + j;
    size_t bRow = (size_t)(n0 + r) * (DH / 8) + j;

    float acc[4][4][4];
#pragma unroll
    for (int a = 0; a < 4; ++a)
#pragma unroll
        for (int b = 0; b < 4; ++b)
#pragma unroll
            for (int c = 0; c < 4; ++c) acc[a][b][c] = 0.0f;

#define ISSUE(it, buf) do {                                                  \
        size_t _ko = (size_t)(it) * 2;                                       \
        uint32_t _d = base + (buf) * STAGEB + dOff;                          \
        cp16(_d,             g_ahi + aRow + _ko, avalid);                    \
        cp16(_d + TILEB,     g_alo + aRow + _ko, avalid);                    \
        cp16(_d + 2 * TILEB, Wh    + bRow + _ko, true);                      \
        cp16(_d + 3 * TILEB, Wl    + bRow + _ko, true);                      \
    } while (0)

    ISSUE(0, 0);
    CP_COMMIT();

    // fragment addresses (per warp, fixed across iters except stage base)
    uint32_t aFragOff[4], bFragOff[2];
#pragma unroll
    for (int mf = 0; mf < 4; ++mf) {
        int row = warp_m + mf * 16 + (lane & 15);
        aFragOff[mf] = (uint32_t)(row * ROWB + (lane >> 4) * 16);
    }
#pragma unroll
    for (int nb = 0; nb < 2; ++nb) {
        int nrow = warp_n + nb * 16 + ((lane >> 4) << 3) + (lane & 7);
        bFragOff[nb] = (uint32_t)(nrow * ROWB + (((lane >> 3) & 1) * 16));
    }

    for (int it = 0; it < NCH; ++it) {
        int buf = it & 1;
        if (it + 1 < NCH) {
            ISSUE(it + 1, buf ^ 1);
            CP_COMMIT();
            CP_WAIT1();
        } else {
            CP_WAIT0();
        }
        __syncthreads();

        uint32_t sb = base + buf * STAGEB;
        uint32_t ahi[4][4], bhi[2][4], blo[2][4];
#pragma unroll
        for (int mf = 0; mf < 4; ++mf) ldmat_x4(ahi[mf], sb + aFragOff[mf]);
#pragma unroll
        for (int nb = 0; nb < 2; ++nb) {
            ldmat_x4(bhi[nb], sb + 2 * TILEB + bFragOff[nb]);
            ldmat_x4(blo[nb], sb + 3 * TILEB + bFragOff[nb]);
        }
        // HH
#pragma unroll
        for (int mf = 0; mf < 4; ++mf)
#pragma unroll
            for (int nf = 0; nf < 4; ++nf)
                mma_bf16(acc[mf][nf], ahi[mf],
                         bhi[nf >> 1][(nf & 1) * 2], bhi[nf >> 1][(nf & 1) * 2 + 1]);
        // HL
#pragma unroll
        for (int mf = 0; mf < 4; ++mf)
#pragma unroll
            for (int nf = 0; nf < 4; ++nf)
                mma_bf16(acc[mf][nf], ahi[mf],
                         blo[nf >> 1][(nf & 1) * 2], blo[nf >> 1][(nf & 1) * 2 + 1]);
        // LH (alo reuses ahi's registers via liveness)
        uint32_t alo[4][4];
#pragma unroll
        for (int mf = 0; mf < 4; ++mf) ldmat_x4(alo[mf], sb + TILEB + aFragOff[mf]);
#pragma unroll
        for (int mf = 0; mf < 4; ++mf)
#pragma unroll
            for (int nf = 0; nf < 4; ++nf)
                mma_bf16(acc[mf][nf], alo[mf],
                         bhi[nf >> 1][(nf & 1) * 2], bhi[nf >> 1][(nf & 1) * 2 + 1]);
    }
#undef ISSUE

    // epilogue
#pragma unroll
    for (int mf = 0; mf < 4; ++mf) {
        int rr = m0 + warp_m + mf * 16 + (lane >> 2);
#pragma unroll
        for (int nf = 0; nf < 4; ++nf) {
            int cc = n0 + warp_n + nf * 8 + (lane & 3) * 2;
            float d0 = acc[mf][nf][0], d1 = acc[mf][nf][1];
            float d2 = acc[mf][nf][2], d3 = acc[mf][nf][3];
            if (extout) {
                if (rr < NNODES) {
                    if (cc < Nvalid)     extout[(size_t)rr * Nvalid + cc]     = d0 + bias[cc];
                    if (cc + 1 < Nvalid) extout[(size_t)rr * Nvalid + cc + 1] = d1 + bias[cc + 1];
                }
                if (rr + 8 < NNODES) {
                    if (cc < Nvalid)     extout[(size_t)(rr + 8) * Nvalid + cc]     = d2 + bias[cc];
                    if (cc + 1 < Nvalid) extout[(size_t)(rr + 8) * Nvalid + cc + 1] = d3 + bias[cc + 1];
                }
            } else {
                if (rr < NNODES)     *(float2*)&g_h[(size_t)rr * DH + cc]       = make_float2(d0, d1);
                if (rr + 8 < NNODES) *(float2*)&g_h[(size_t)(rr + 8) * DH + cc] = make_float2(d2, d3);
            }
        }
    }
}

// ---------------------------------------------------------------------------
// Aggregation: one block per node; writes split bf16 for next GEMM.
// ---------------------------------------------------------------------------
__global__ __launch_bounds__(128) void agg_kernel(
    const float* __restrict__ bias, int relu)
{
    int i = blockIdx.x;
    int tid = threadIdx.x;
    const float4* h4 = (const float4*)g_h;
    float di = g_dinv[i];
    int beg = g_rowptr[i];
    int end = g_rowptr[i + 1];

    float4 acc = make_float4(0.f, 0.f, 0.f, 0.f);
    for (int jj = beg; jj < end; ++jj) {
        int s = g_col[jj];
        float w = g_dinv[s] * di;
        float4 v = h4[(size_t)s * (DH / 4) + tid];
        acc.x += v.x * w;
        acc.y += v.y * w;
        acc.z += v.z * w;
        acc.w += v.w * w;
    }
    float sw = di * di;
    float4 self = h4[(size_t)i * (DH / 4) + tid];
    acc.x += self.x * sw;
    acc.y += self.y * sw;
    acc.z += self.z * sw;
    acc.w += self.w * sw;
    const float4* b4 = (const float4*)bias;
    float4 bb = b4[tid];
    acc.x += bb.x; acc.y += bb.y; acc.z += bb.z; acc.w += bb.w;
    if (relu) {
        acc.x = fmaxf(acc.x, 0.f);
        acc.y = fmaxf(acc.y, 0.f);
        acc.z = fmaxf(acc.z, 0.f);
        acc.w = fmaxf(acc.w, 0.f);
    }
    float v[4] = {acc.x, acc.y, acc.z, acc.w};
    __nv_bfloat16 hi[4], lo[4];
#pragma unroll
    for (int jj = 0; jj < 4; ++jj) split_bf16(v[jj], hi[jj], lo[jj]);
    ((uint2*)g_ahi)[(size_t)i * (DH / 4) + tid] = *(uint2*)hi;
    ((uint2*)g_alo)[(size_t)i * (DH / 4) + tid] = *(uint2*)lo;
}

// ---------------------------------------------------------------------------
extern "C" void kernel_launch(void* const* d_in, const int* in_sizes, int n_in,
                              void* d_out, int out_size) {
    const float* x  = (const float*)d_in[0];
    const int*   ei = (const int*)d_in[1];     // int32 (JAX x64 disabled)
    const float* W1 = (const float*)d_in[2];
    const float* b1 = (const float*)d_in[3];
    const float* W2 = (const float*)d_in[4];
    const float* b2 = (const float*)d_in[5];
    const float* Wc = (const float*)d_in[6];
    const float* bc = (const float*)d_in[7];
    float* out = (float*)d_out;

    int N = in_sizes[0] / DH;             // 10000
    int E = in_sizes[1] / 2;              // 160000
    int d_out_dim = in_sizes[6] / DH;     // 100

    // CSR build
    zero_cnt_kernel<<<(N + 255) / 256, 256>>>(N);
    count_kernel<<<(E + 255) / 256, 256>>>(ei, E, N);
    scan_kernel<<<1, 1024>>>(N);
    fill_kernel<<<(E + 255) / 256, 256>>>(ei, E, N);

    // operand prep
    conv_x_kernel<<<(N * DH / 8 + 255) / 256, 256>>>(x);
    dim3 tb(32, 32);
    prep_w_kernel<<<dim3(DH / 32, DH / 32), tb>>>(W1, DH, 0);
    prep_w_kernel<<<dim3(DH / 32, DH / 32), tb>>>(W2, DH, 1);
    prep_w_kernel<<<dim3(DH / 32, NPADC / 32), tb>>>(Wc, d_out_dim, 2);

    int mblocks = (N + BMt - 1) / BMt;    // 79

    // Layer 1
    mma_gemm_kernel<<<dim3(DH / BNt, mblocks), 256>>>(0, nullptr, nullptr, DH);
    agg_kernel<<<N, 128>>>(b1, 1);

    // Layer 2
    mma_gemm_kernel<<<dim3(DH / BNt, mblocks), 256>>>(1, nullptr, nullptr, DH);
    agg_kernel<<<N, 128>>>(b2, 0);

    // Classifier
    mma_gemm_kernel<<<dim3(1, mblocks), 256>>>(2, bc, out, d_out_dim);
}